// round 8
// baseline (speedup 1.0000x reference)
#include <cuda_runtime.h>
#include <cuda_bf16.h>
#include <cstdint>

#define NN 100000
#define DD 128
#define EE 600000
#define NT64 1563  // ceil(NN/64)

// ---------------- scratch (device globals: no runtime allocation) ----------------
__device__ float g_h[(size_t)NN * DD];
__device__ float g_agg[(size_t)NN * DD];     // scatter(h)
__device__ float g_gh[(size_t)NN * 3 * DD];  // h @ Whh^T + bhh
__device__ float g_rz[(size_t)NN * 2 * DD];  // r,z gate scratch for fused GRU
__device__ float g_wf[3 * 384 * 128];        // Wfused[l] = Wih @ Wconv[l]
// pre-split, pre-swizzled weights: 16 tiles of 128x128 bf16 (32KB blobs)
// tile order: W1 (0), Whh (1-3), W2 (4-6), Wfused (7-15)
__device__ __nv_bfloat16 g_whi[16 * 16384];
__device__ __nv_bfloat16 g_wlo[16 * 16384];

// ---------------- helpers ----------------
static __device__ __forceinline__ uint32_t smem_u32(const void* p) {
    uint32_t a;
    asm("{ .reg .u64 t; cvta.to.shared.u64 t, %1; cvt.u32.u64 %0, t; }" : "=r"(a) : "l"(p));
    return a;
}
static __device__ __forceinline__ void ldsm4(uint32_t* r, uint32_t addr) {
    asm volatile("ldmatrix.sync.aligned.m8n8.x4.shared.b16 {%0,%1,%2,%3}, [%4];"
                 : "=r"(r[0]), "=r"(r[1]), "=r"(r[2]), "=r"(r[3]) : "r"(addr));
}
static __device__ __forceinline__ void mma16816(float* d, const uint32_t* a, const uint32_t* b) {
    asm volatile(
        "mma.sync.aligned.m16n8k16.row.col.f32.bf16.bf16.f32 "
        "{%0,%1,%2,%3}, {%4,%5,%6,%7}, {%8,%9}, {%0,%1,%2,%3};"
        : "+f"(d[0]), "+f"(d[1]), "+f"(d[2]), "+f"(d[3])
        : "r"(a[0]), "r"(a[1]), "r"(a[2]), "r"(a[3]), "r"(b[0]), "r"(b[1]));
}
static __device__ __forceinline__ void cpa16(uint32_t dst, const void* src) {
    asm volatile("cp.async.cg.shared.global [%0], [%1], 16;" :: "r"(dst), "l"(src) : "memory");
}
#define CP_COMMIT_WAIT() \
    asm volatile("cp.async.commit_group;\ncp.async.wait_group 0;" ::: "memory")

// swizzled byte offset within a tile (rows of 256B; 16B chunks XOR'd by row)
static __device__ __forceinline__ uint32_t swz(uint32_t r, uint32_t c2) {
    return r * 256 + (c2 ^ ((r & 7) << 4));
}

// Dekker split of 4 floats into bf16 hi/lo packed words
static __device__ __forceinline__ void split4(float4 v, uint2& hi, uint2& lo) {
    __nv_bfloat16 h0 = __float2bfloat16(v.x), h1 = __float2bfloat16(v.y);
    __nv_bfloat16 h2 = __float2bfloat16(v.z), h3 = __float2bfloat16(v.w);
    __nv_bfloat16 l0 = __float2bfloat16(v.x - __bfloat162float(h0));
    __nv_bfloat16 l1 = __float2bfloat16(v.y - __bfloat162float(h1));
    __nv_bfloat16 l2 = __float2bfloat16(v.z - __bfloat162float(h2));
    __nv_bfloat16 l3 = __float2bfloat16(v.w - __bfloat162float(h3));
    hi.x = (uint32_t)__bfloat16_as_ushort(h0) | ((uint32_t)__bfloat16_as_ushort(h1) << 16);
    hi.y = (uint32_t)__bfloat16_as_ushort(h2) | ((uint32_t)__bfloat16_as_ushort(h3) << 16);
    lo.x = (uint32_t)__bfloat16_as_ushort(l0) | ((uint32_t)__bfloat16_as_ushort(l1) << 16);
    lo.y = (uint32_t)__bfloat16_as_ushort(l2) | ((uint32_t)__bfloat16_as_ushort(l3) << 16);
}

static __device__ __forceinline__ float sigf(float x) { return 1.f / (1.f + __expf(-x)); }

// ---------------- prepass 1: Wfused[l] = Wih @ Wconv[l]  (fp32) ----------------
__global__ void wfused_kernel(const float* __restrict__ Wih, const float* __restrict__ Wconv) {
    int i = blockIdx.x * blockDim.x + threadIdx.x;  // 3*384*128
    if (i >= 3 * 384 * 128) return;
    int l = i / (384 * 128), r = (i >> 7) % 384, k = i & 127;
    const float* wc = Wconv + (size_t)l * 128 * 128;
    float s = 0.f;
#pragma unroll 8
    for (int j = 0; j < 128; j++) s = fmaf(__ldg(Wih + r * 128 + j), __ldg(wc + j * 128 + k), s);
    g_wf[i] = s;
}

// ---------------- prepass 2: split + swizzle all 16 weight tiles ----------------
// rows: [0,128) W1; [128,512) Whh; [512,896) W2; [896,2048) Wfused
__global__ void convert_w(const float* __restrict__ W1, const float* __restrict__ Whh,
                          const float* __restrict__ W2) {
    int i = blockIdx.x * blockDim.x + threadIdx.x;  // 2048*128 elements
    if (i >= 2048 * 128) return;
    int row = i >> 7, k = i & 127;
    float v;
    if (row < 128)       v = W1[(size_t)row * 128 + k];
    else if (row < 512)  v = Whh[(size_t)(row - 128) * 128 + k];
    else if (row < 896)  v = W2[(size_t)(row - 512) * 128 + k];
    else                 v = g_wf[(size_t)(row - 896) * 128 + k];
    __nv_bfloat16 h = __float2bfloat16(v);
    __nv_bfloat16 l = __float2bfloat16(v - __bfloat162float(h));
    int tile = row >> 7, tr = row & 127;
    uint32_t o = swz((uint32_t)tr, (uint32_t)(2 * k));
    *(__nv_bfloat16*)((char*)g_whi + (size_t)tile * 32768 + o) = h;
    *(__nv_bfloat16*)((char*)g_wlo + (size_t)tile * 32768 + o) = l;
}

// SMEM: A hi/lo (64x128 = 16KB each), B hi/lo (128x128 = 32KB each) = 96KB
#define SM_A_HI 0
#define SM_A_LO 16384
#define SM_B_HI 32768
#define SM_B_LO 65536
#define SM_TOTAL 98304

// ======== mma.sync GEMM: C[N, MT*128] = act( A[N,128] @ W^T + b ) ========
// Tile 64(M) x 128(N); 8 warps = 2 row x 4 col, warp tile 32x32; 3-term bf16 split.
// Restructured inner loop: per k-step hoist A_hi/A_lo/B_hi/B_lo frags (8 ldsm4),
// then issue 24 MMAs (hi*hi + hi*lo + lo*hi).
// FUSE=1 (requires MT=3, BIAS=1): GRU epilogue per mt-tile; C is the h buffer.
template <int ACTIN, int ACTOUT, int BIAS, int MT, int FUSE>
__global__ __launch_bounds__(256, 2)
void gemm_mma(const float* __restrict__ A, int wtile0,
              const float* __restrict__ bias, float* __restrict__ C,
              const float* __restrict__ gh, float* __restrict__ rz) {
    extern __shared__ char smem[];
    const uint32_t sb = smem_u32(smem);
    const int tid = threadIdx.x, lane = tid & 31, wid = tid >> 5;
    const int warp_m = (wid & 1) * 32;
    const int warp_n = (wid >> 1) * 32;
    const int n0 = blockIdx.x * 64;

    const int a_row = lane & 15;
    const int a_kh = (lane >> 4) & 1;
    const int b_row = (lane & 7) | (((lane >> 4) & 1) << 3);
    const int b_kh = (lane >> 3) & 1;

    // ---- fill + split A tile (64 rows x 128 k), once per CTA ----
    for (int i = tid; i < 2048; i += 256) {
        int r = i >> 5, k = (i & 31) << 2;
        int gr = n0 + r;
        if (gr >= NN) gr = NN - 1;  // clamp; padded rows discarded at store
        float4 v = *(const float4*)(A + (size_t)gr * 128 + k);
        if (ACTIN) {
            v.x = fmaxf(v.x, 0.f); v.y = fmaxf(v.y, 0.f);
            v.z = fmaxf(v.z, 0.f); v.w = fmaxf(v.w, 0.f);
        }
        uint2 hi, lo;
        split4(v, hi, lo);
        uint32_t o = swz((uint32_t)r, (uint32_t)(k * 2));
        *(uint2*)(smem + SM_A_HI + o) = hi;
        *(uint2*)(smem + SM_A_LO + o) = lo;
    }

    for (int mt = 0; mt < MT; mt++) {
        // ---- W fill: identity cp.async copy of pre-swizzled blobs ----
        const char* whb = (const char*)g_whi + (size_t)(wtile0 + mt) * 32768;
        const char* wlb = (const char*)g_wlo + (size_t)(wtile0 + mt) * 32768;
        for (int i = tid; i < 2048; i += 256) {
            cpa16(sb + SM_B_HI + i * 16, whb + i * 16);
            cpa16(sb + SM_B_LO + i * 16, wlb + i * 16);
        }
        CP_COMMIT_WAIT();
        __syncthreads();

        float acc[2][4][4];
#pragma unroll
        for (int t = 0; t < 2; t++)
#pragma unroll
            for (int u = 0; u < 4; u++)
#pragma unroll
                for (int q = 0; q < 4; q++) acc[t][u][q] = 0.f;

#pragma unroll
        for (int ks = 0; ks < 8; ks++) {
            const uint32_t c2a = ks * 32 + a_kh * 16;
            const uint32_t c2b = ks * 32 + b_kh * 16;
            uint32_t ah[2][4], al[2][4], bh[4][2], bl[4][2];
#pragma unroll
            for (int t = 0; t < 2; t++) {
                ldsm4(ah[t], sb + SM_A_HI + swz(warp_m + t * 16 + a_row, c2a));
                ldsm4(al[t], sb + SM_A_LO + swz(warp_m + t * 16 + a_row, c2a));
            }
#pragma unroll
            for (int ub = 0; ub < 2; ub++) {
                uint32_t tmp[4];
                ldsm4(tmp, sb + SM_B_HI + swz(warp_n + ub * 16 + b_row, c2b));
                bh[2 * ub][0] = tmp[0]; bh[2 * ub][1] = tmp[1];
                bh[2 * ub + 1][0] = tmp[2]; bh[2 * ub + 1][1] = tmp[3];
                ldsm4(tmp, sb + SM_B_LO + swz(warp_n + ub * 16 + b_row, c2b));
                bl[2 * ub][0] = tmp[0]; bl[2 * ub][1] = tmp[1];
                bl[2 * ub + 1][0] = tmp[2]; bl[2 * ub + 1][1] = tmp[3];
            }
#pragma unroll
            for (int t = 0; t < 2; t++)
#pragma unroll
                for (int u = 0; u < 4; u++) mma16816(acc[t][u], ah[t], bh[u]);
#pragma unroll
            for (int t = 0; t < 2; t++)
#pragma unroll
                for (int u = 0; u < 4; u++) mma16816(acc[t][u], ah[t], bl[u]);
#pragma unroll
            for (int t = 0; t < 2; t++)
#pragma unroll
                for (int u = 0; u < 4; u++) mma16816(acc[t][u], al[t], bh[u]);
        }

        // ---- epilogue ----
        const int row0 = n0 + warp_m + (lane >> 2);
        if (FUSE) {
            // GRU gate epilogue: mt0 -> r, mt1 -> z, mt2 -> n + combine, write h'
#pragma unroll
            for (int u = 0; u < 4; u++) {
                const int cin = warp_n + (lane & 3) * 2 + u * 8;  // col within gate
                const int cg = mt * 128 + cin;                    // global col in [0,384)
                const float bi0 = __ldg(bias + cg), bi1 = __ldg(bias + cg + 1);
#pragma unroll
                for (int t = 0; t < 2; t++) {
#pragma unroll
                    for (int hrow = 0; hrow < 2; hrow++) {
                        const int r = row0 + t * 16 + hrow * 8;
                        if (r >= NN) continue;
                        const float v0 = acc[t][u][2 * hrow + 0];
                        const float v1 = acc[t][u][2 * hrow + 1];
                        const float2 g = *(const float2*)(gh + (size_t)r * 384 + cg);
                        if (mt < 2) {
                            float2 o;
                            o.x = sigf(v0 + bi0 + g.x);
                            o.y = sigf(v1 + bi1 + g.y);
                            *(float2*)(rz + (size_t)r * 256 + mt * 128 + cin) = o;
                        } else {
                            const float2 rr = *(const float2*)(rz + (size_t)r * 256 + cin);
                            const float2 zz = *(const float2*)(rz + (size_t)r * 256 + 128 + cin);
                            float2* hp = (float2*)(C + (size_t)r * 128 + cin);
                            const float2 hv = *hp;
                            const float n0v = tanhf(v0 + bi0 + rr.x * g.x);
                            const float n1v = tanhf(v1 + bi1 + rr.y * g.y);
                            float2 o;
                            o.x = (1.f - zz.x) * n0v + zz.x * hv.x;
                            o.y = (1.f - zz.y) * n1v + zz.y * hv.y;
                            *hp = o;
                        }
                    }
                }
            }
        } else {
            const int M = MT * 128;
            const int colb = mt * 128 + warp_n + (lane & 3) * 2;
#pragma unroll
            for (int u = 0; u < 4; u++) {
                const int c = colb + u * 8;
                float b0 = 0.f, b1 = 0.f;
                if (BIAS) { b0 = __ldg(bias + c); b1 = __ldg(bias + c + 1); }
#pragma unroll
                for (int t = 0; t < 2; t++) {
                    const int r = row0 + t * 16;
                    float v0 = acc[t][u][0] + b0, v1 = acc[t][u][1] + b1;
                    float v2 = acc[t][u][2] + b0, v3 = acc[t][u][3] + b1;
                    if (ACTOUT) {
                        v0 = fmaxf(v0, 0.f); v1 = fmaxf(v1, 0.f);
                        v2 = fmaxf(v2, 0.f); v3 = fmaxf(v3, 0.f);
                    }
                    if (r < NN) *(float2*)(C + (size_t)r * M + c) = make_float2(v0, v1);
                    if (r + 8 < NN) *(float2*)(C + (size_t)(r + 8) * M + c) = make_float2(v2, v3);
                }
            }
        }
        if (MT > 1) __syncthreads();  // B consumed before next mt overwrites
    }
}

// ---------------- zero agg ----------------
__global__ void zero_kernel(float4* __restrict__ p) {
    int i = blockIdx.x * blockDim.x + threadIdx.x;
    p[i] = make_float4(0.f, 0.f, 0.f, 0.f);
}

// ---------------- scatter-add: agg[dst] += h[src], warp per edge (REDG v4) ----------------
__global__ void scatter_kernel(const float* __restrict__ h,
                               const void* __restrict__ ei_raw,
                               float* __restrict__ agg) {
    int t = blockIdx.x * blockDim.x + threadIdx.x;
    int e = t >> 5;
    int lane = t & 31;
    if (e >= EE) return;

    const long long* e64 = (const long long*)ei_raw;
    bool is64 = (((unsigned long long)e64[0] < (unsigned long long)NN) &&
                 ((unsigned long long)e64[1] < (unsigned long long)NN));
    int src, dst;
    if (is64) {
        src = (int)e64[e];
        dst = (int)e64[EE + e];
    } else {
        const int* e32 = (const int*)ei_raw;
        src = e32[e];
        dst = e32[EE + e];
    }
    float4 v = *(const float4*)(h + (size_t)src * DD + lane * 4);
    float* p = agg + (size_t)dst * DD + lane * 4;
    asm volatile("red.global.add.v4.f32 [%0], {%1, %2, %3, %4};"
                 :: "l"(p), "f"(v.x), "f"(v.y), "f"(v.z), "f"(v.w)
                 : "memory");
}

// ---------------- launcher ----------------
extern "C" void kernel_launch(void* const* d_in, const int* in_sizes, int n_in,
                              void* d_out, int out_size) {
    const float* x     = (const float*)d_in[0];
    const void*  ei    = (const void*)d_in[1];
    const float* W1    = (const float*)d_in[2];
    const float* b1    = (const float*)d_in[3];
    const float* Wconv = (const float*)d_in[4];
    const float* Wih   = (const float*)d_in[5];
    const float* Whh   = (const float*)d_in[6];
    const float* bih   = (const float*)d_in[7];
    const float* bhh   = (const float*)d_in[8];
    const float* W2    = (const float*)d_in[9];
    const float* b2    = (const float*)d_in[10];
    float* out = (float*)d_out;

    float *h, *agg, *gh, *rz;
    cudaGetSymbolAddress((void**)&h, g_h);
    cudaGetSymbolAddress((void**)&agg, g_agg);
    cudaGetSymbolAddress((void**)&gh, g_gh);
    cudaGetSymbolAddress((void**)&rz, g_rz);

    cudaFuncSetAttribute(gemm_mma<0, 1, 1, 1, 0>, cudaFuncAttributeMaxDynamicSharedMemorySize, SM_TOTAL);
    cudaFuncSetAttribute(gemm_mma<0, 0, 1, 3, 0>, cudaFuncAttributeMaxDynamicSharedMemorySize, SM_TOTAL);
    cudaFuncSetAttribute(gemm_mma<1, 0, 1, 3, 0>, cudaFuncAttributeMaxDynamicSharedMemorySize, SM_TOTAL);
    cudaFuncSetAttribute(gemm_mma<0, 0, 1, 3, 1>, cudaFuncAttributeMaxDynamicSharedMemorySize, SM_TOTAL);

    // side stream + fork/join events (created and destroyed every call; capture-safe)
    cudaStream_t s2;
    cudaStreamCreateWithFlags(&s2, cudaStreamNonBlocking);
    cudaEvent_t evH[3], evG[3];
    for (int i = 0; i < 3; i++) {
        cudaEventCreateWithFlags(&evH[i], cudaEventDisableTiming);
        cudaEventCreateWithFlags(&evG[i], cudaEventDisableTiming);
    }

    // prepasses: Wfused then split+swizzle all 16 tiles
    wfused_kernel<<<(3 * 384 * 128 + 255) / 256, 256>>>(Wih, Wconv);
    convert_w<<<(2048 * 128 + 255) / 256, 256>>>(W1, Whh, W2);

    // h = relu(x @ W1^T + b1)
    gemm_mma<0, 1, 1, 1, 0><<<NT64, 256, SM_TOTAL>>>(x, 0, b1, h, nullptr, nullptr);

    for (int l = 0; l < 3; l++) {
        // fork: gh = h @ Whh^T + bhh on s2, overlapping zero+scatter on main
        cudaEventRecord(evH[l], 0);
        cudaStreamWaitEvent(s2, evH[l], 0);
        gemm_mma<0, 0, 1, 3, 0><<<NT64, 256, SM_TOTAL, s2>>>(h, 1, bhh, gh, nullptr, nullptr);
        cudaEventRecord(evG[l], s2);

        // main: agg = scatter(h)
        zero_kernel<<<NN * DD / 4 / 256, 256>>>((float4*)agg);
        scatter_kernel<<<(EE * 32) / 256, 256>>>(h, ei, agg);

        // join, then fused gi GEMM + GRU -> writes h in place
        cudaStreamWaitEvent(0, evG[l], 0);
        gemm_mma<0, 0, 1, 3, 1><<<NT64, 256, SM_TOTAL>>>(agg, 7 + 3 * l, bih, h, gh, rz);
    }

    // out = relu(h) @ W2^T + b2
    gemm_mma<1, 0, 1, 3, 0><<<NT64, 256, SM_TOTAL>>>(h, 4, b2, out, nullptr, nullptr);

    for (int i = 0; i < 3; i++) {
        cudaEventDestroy(evH[i]);
        cudaEventDestroy(evG[i]);
    }
    cudaStreamDestroy(s2);
}

// round 9
// speedup vs baseline: 1.1314x; 1.1314x over previous
#include <cuda_runtime.h>
#include <cuda_bf16.h>
#include <cstdint>

#define NN 100000
#define DD 128
#define EE 600000
#define NT64 1563  // ceil(NN/64)

// ---------------- scratch (device globals: no runtime allocation) ----------------
__device__ float g_h[(size_t)NN * DD];
__device__ float g_agg[(size_t)NN * DD];     // scatter(h)
__device__ float g_gi[(size_t)NN * 3 * DD];
__device__ float g_gh[(size_t)NN * 3 * DD];
__device__ float g_wf[3 * 384 * 128];        // Wfused[l] = Wih @ Wconv[l]
// pre-split, pre-swizzled weights: 16 tiles of 128x128 bf16 (32KB blobs)
// tile order: W1 (0), Whh (1-3), W2 (4-6), Wfused (7-15)
__device__ __nv_bfloat16 g_whi[16 * 16384];
__device__ __nv_bfloat16 g_wlo[16 * 16384];

// ---------------- helpers ----------------
static __device__ __forceinline__ uint32_t smem_u32(const void* p) {
    uint32_t a;
    asm("{ .reg .u64 t; cvta.to.shared.u64 t, %1; cvt.u32.u64 %0, t; }" : "=r"(a) : "l"(p));
    return a;
}
static __device__ __forceinline__ void ldsm4(uint32_t* r, uint32_t addr) {
    asm volatile("ldmatrix.sync.aligned.m8n8.x4.shared.b16 {%0,%1,%2,%3}, [%4];"
                 : "=r"(r[0]), "=r"(r[1]), "=r"(r[2]), "=r"(r[3]) : "r"(addr));
}
static __device__ __forceinline__ void mma16816(float* d, const uint32_t* a, const uint32_t* b) {
    asm volatile(
        "mma.sync.aligned.m16n8k16.row.col.f32.bf16.bf16.f32 "
        "{%0,%1,%2,%3}, {%4,%5,%6,%7}, {%8,%9}, {%0,%1,%2,%3};"
        : "+f"(d[0]), "+f"(d[1]), "+f"(d[2]), "+f"(d[3])
        : "r"(a[0]), "r"(a[1]), "r"(a[2]), "r"(a[3]), "r"(b[0]), "r"(b[1]));
}
static __device__ __forceinline__ void cpa16(uint32_t dst, const void* src) {
    asm volatile("cp.async.cg.shared.global [%0], [%1], 16;" :: "r"(dst), "l"(src) : "memory");
}
#define CP_COMMIT() asm volatile("cp.async.commit_group;" ::: "memory")
#define CP_WAIT0()  asm volatile("cp.async.wait_group 0;" ::: "memory")
#define CP_WAIT1()  asm volatile("cp.async.wait_group 1;" ::: "memory")

// swizzled byte offset within a tile (rows of 256B; 16B chunks XOR'd by row)
static __device__ __forceinline__ uint32_t swz(uint32_t r, uint32_t c2) {
    return r * 256 + (c2 ^ ((r & 7) << 4));
}

// Dekker split of 4 floats into bf16 hi/lo packed words
static __device__ __forceinline__ void split4(float4 v, uint2& hi, uint2& lo) {
    __nv_bfloat16 h0 = __float2bfloat16(v.x), h1 = __float2bfloat16(v.y);
    __nv_bfloat16 h2 = __float2bfloat16(v.z), h3 = __float2bfloat16(v.w);
    __nv_bfloat16 l0 = __float2bfloat16(v.x - __bfloat162float(h0));
    __nv_bfloat16 l1 = __float2bfloat16(v.y - __bfloat162float(h1));
    __nv_bfloat16 l2 = __float2bfloat16(v.z - __bfloat162float(h2));
    __nv_bfloat16 l3 = __float2bfloat16(v.w - __bfloat162float(h3));
    hi.x = (uint32_t)__bfloat16_as_ushort(h0) | ((uint32_t)__bfloat16_as_ushort(h1) << 16);
    hi.y = (uint32_t)__bfloat16_as_ushort(h2) | ((uint32_t)__bfloat16_as_ushort(h3) << 16);
    lo.x = (uint32_t)__bfloat16_as_ushort(l0) | ((uint32_t)__bfloat16_as_ushort(l1) << 16);
    lo.y = (uint32_t)__bfloat16_as_ushort(l2) | ((uint32_t)__bfloat16_as_ushort(l3) << 16);
}

static __device__ __forceinline__ float sigf(float x) { return 1.f / (1.f + __expf(-x)); }

// ---------------- prepass 1: Wfused[l] = Wih @ Wconv[l]  (fp32) ----------------
__global__ void wfused_kernel(const float* __restrict__ Wih, const float* __restrict__ Wconv) {
    int i = blockIdx.x * blockDim.x + threadIdx.x;  // 3*384*128
    if (i >= 3 * 384 * 128) return;
    int l = i / (384 * 128), r = (i >> 7) % 384, k = i & 127;
    const float* wc = Wconv + (size_t)l * 128 * 128;
    float s = 0.f;
#pragma unroll 8
    for (int j = 0; j < 128; j++) s = fmaf(__ldg(Wih + r * 128 + j), __ldg(wc + j * 128 + k), s);
    g_wf[i] = s;
}

// ---------------- prepass 2: split + swizzle all 16 weight tiles ----------------
// rows: [0,128) W1; [128,512) Whh; [512,896) W2; [896,2048) Wfused
__global__ void convert_w(const float* __restrict__ W1, const float* __restrict__ Whh,
                          const float* __restrict__ W2) {
    int i = blockIdx.x * blockDim.x + threadIdx.x;  // 2048*128 elements
    if (i >= 2048 * 128) return;
    int row = i >> 7, k = i & 127;
    float v;
    if (row < 128)       v = W1[(size_t)row * 128 + k];
    else if (row < 512)  v = Whh[(size_t)(row - 128) * 128 + k];
    else if (row < 896)  v = W2[(size_t)(row - 512) * 128 + k];
    else                 v = g_wf[(size_t)(row - 896) * 128 + k];
    __nv_bfloat16 h = __float2bfloat16(v);
    __nv_bfloat16 l = __float2bfloat16(v - __bfloat162float(h));
    int tile = row >> 7, tr = row & 127;
    uint32_t o = swz((uint32_t)tr, (uint32_t)(2 * k));
    *(__nv_bfloat16*)((char*)g_whi + (size_t)tile * 32768 + o) = h;
    *(__nv_bfloat16*)((char*)g_wlo + (size_t)tile * 32768 + o) = l;
}

// SMEM: A hi/lo (64x128 = 16KB each), B hi/lo (128x128 = 32KB each) = 96KB
#define SM_A_HI 0
#define SM_A_LO 16384
#define SM_B_HI 32768
#define SM_B_LO 65536
#define SM_TOTAL 98304

// one split-pass: acc += A(Abase) @ B(Bbase)^T over full K=128 (8 k-steps)
static __device__ __forceinline__ void mma_pass(
    float acc[2][4][4], uint32_t Abase, uint32_t Bbase,
    int warp_m, int warp_n, int a_row, int a_kh, int b_row, int b_kh) {
#pragma unroll
    for (int ks = 0; ks < 8; ks++) {
        const uint32_t c2a = ks * 32 + a_kh * 16;
        const uint32_t c2b = ks * 32 + b_kh * 16;
        uint32_t af[2][4], bf[4][2];
#pragma unroll
        for (int t = 0; t < 2; t++)
            ldsm4(af[t], Abase + swz(warp_m + t * 16 + a_row, c2a));
#pragma unroll
        for (int ub = 0; ub < 2; ub++) {
            uint32_t tmp[4];
            ldsm4(tmp, Bbase + swz(warp_n + ub * 16 + b_row, c2b));
            bf[2 * ub][0] = tmp[0]; bf[2 * ub][1] = tmp[1];
            bf[2 * ub + 1][0] = tmp[2]; bf[2 * ub + 1][1] = tmp[3];
        }
#pragma unroll
        for (int t = 0; t < 2; t++)
#pragma unroll
            for (int u = 0; u < 4; u++)
                mma16816(acc[t][u], af[t], bf[u]);
    }
}

// ======== mma.sync GEMM: C[N, MT*128] = act( A[N,128] @ W^T + b ) ========
// Tile 64(M) x 128(N); 8 warps = 2 row x 4 col, warp tile 32x32; 3-term bf16 split.
// B-fill pipelined: passes ordered (hihi, lohi | hilo); next mt's B_hi prefetched
// during pass 3, next B_lo prefetched during the epilogue (in-place, cp.async FIFO).
template <int ACTIN, int ACTOUT, int BIAS, int MT>
__global__ __launch_bounds__(256, 2)
void gemm_mma(const float* __restrict__ A, int wtile0,
              const float* __restrict__ bias, float* __restrict__ C) {
    extern __shared__ char smem[];
    const uint32_t sb = smem_u32(smem);
    const int tid = threadIdx.x, lane = tid & 31, wid = tid >> 5;
    const int warp_m = (wid & 1) * 32;
    const int warp_n = (wid >> 1) * 32;
    const int n0 = blockIdx.x * 64;

    const int a_row = lane & 15;
    const int a_kh = (lane >> 4) & 1;
    const int b_row = (lane & 7) | (((lane >> 4) & 1) << 3);
    const int b_kh = (lane >> 3) & 1;

    // ---- prefetch B(0): hi then lo, separate groups (FIFO) ----
    {
        const char* whb = (const char*)g_whi + (size_t)wtile0 * 32768;
        const char* wlb = (const char*)g_wlo + (size_t)wtile0 * 32768;
        for (int i = tid; i < 2048; i += 256) cpa16(sb + SM_B_HI + i * 16, whb + i * 16);
        CP_COMMIT();
        for (int i = tid; i < 2048; i += 256) cpa16(sb + SM_B_LO + i * 16, wlb + i * 16);
        CP_COMMIT();
    }

    // ---- fill + split A tile (64 rows x 128 k), overlaps the B cp.asyncs ----
    for (int i = tid; i < 2048; i += 256) {
        int r = i >> 5, k = (i & 31) << 2;
        int gr = n0 + r;
        if (gr >= NN) gr = NN - 1;  // clamp; padded rows discarded at store
        float4 v = *(const float4*)(A + (size_t)gr * 128 + k);
        if (ACTIN) {
            v.x = fmaxf(v.x, 0.f); v.y = fmaxf(v.y, 0.f);
            v.z = fmaxf(v.z, 0.f); v.w = fmaxf(v.w, 0.f);
        }
        uint2 hi, lo;
        split4(v, hi, lo);
        uint32_t o = swz((uint32_t)r, (uint32_t)(k * 2));
        *(uint2*)(smem + SM_A_HI + o) = hi;
        *(uint2*)(smem + SM_A_LO + o) = lo;
    }

    for (int mt = 0; mt < MT; mt++) {
        // wait B_hi(mt) (oldest pending group); B_lo(mt) may still be in flight
        CP_WAIT1();
        __syncthreads();

        float acc[2][4][4];
#pragma unroll
        for (int t = 0; t < 2; t++)
#pragma unroll
            for (int u = 0; u < 4; u++)
#pragma unroll
                for (int q = 0; q < 4; q++) acc[t][u][q] = 0.f;

        // passes 1-2: consume B_hi
        mma_pass(acc, sb + SM_A_HI, sb + SM_B_HI, warp_m, warp_n, a_row, a_kh, b_row, b_kh);
        mma_pass(acc, sb + SM_A_LO, sb + SM_B_HI, warp_m, warp_n, a_row, a_kh, b_row, b_kh);
        __syncthreads();  // all warps done reading B_hi

        // prefetch next B_hi during pass 3
        if (mt + 1 < MT) {
            const char* whb = (const char*)g_whi + (size_t)(wtile0 + mt + 1) * 32768;
            for (int i = tid; i < 2048; i += 256) cpa16(sb + SM_B_HI + i * 16, whb + i * 16);
            CP_COMMIT();
            CP_WAIT1();  // B_lo(mt) done (older than B_hi(mt+1))
        } else {
            CP_WAIT0();  // last tile: just finish B_lo(mt)
        }
        __syncthreads();

        // pass 3: consume B_lo
        mma_pass(acc, sb + SM_A_HI, sb + SM_B_LO, warp_m, warp_n, a_row, a_kh, b_row, b_kh);
        __syncthreads();  // all warps done reading B_lo

        // prefetch next B_lo during the epilogue
        if (mt + 1 < MT) {
            const char* wlb = (const char*)g_wlo + (size_t)(wtile0 + mt + 1) * 32768;
            for (int i = tid; i < 2048; i += 256) cpa16(sb + SM_B_LO + i * 16, wlb + i * 16);
            CP_COMMIT();
        }

        // ---- epilogue ----
        const int M = MT * 128;
        const int row0 = n0 + warp_m + (lane >> 2);
        const int colb = mt * 128 + warp_n + (lane & 3) * 2;
#pragma unroll
        for (int u = 0; u < 4; u++) {
            const int c = colb + u * 8;
            float b0 = 0.f, b1 = 0.f;
            if (BIAS) { b0 = __ldg(bias + c); b1 = __ldg(bias + c + 1); }
#pragma unroll
            for (int t = 0; t < 2; t++) {
                const int r = row0 + t * 16;
                float v0 = acc[t][u][0] + b0, v1 = acc[t][u][1] + b1;
                float v2 = acc[t][u][2] + b0, v3 = acc[t][u][3] + b1;
                if (ACTOUT) {
                    v0 = fmaxf(v0, 0.f); v1 = fmaxf(v1, 0.f);
                    v2 = fmaxf(v2, 0.f); v3 = fmaxf(v3, 0.f);
                }
                if (r < NN) *(float2*)(C + (size_t)r * M + c) = make_float2(v0, v1);
                if (r + 8 < NN) *(float2*)(C + (size_t)(r + 8) * M + c) = make_float2(v2, v3);
            }
        }
    }
}

// ---------------- zero agg ----------------
__global__ void zero_kernel(float4* __restrict__ p) {
    int i = blockIdx.x * blockDim.x + threadIdx.x;
    p[i] = make_float4(0.f, 0.f, 0.f, 0.f);
}

// ---------------- scatter-add: agg[dst] += h[src], warp per edge (REDG v4) ----------------
__global__ void scatter_kernel(const float* __restrict__ h,
                               const void* __restrict__ ei_raw,
                               float* __restrict__ agg) {
    int t = blockIdx.x * blockDim.x + threadIdx.x;
    int e = t >> 5;
    int lane = t & 31;
    if (e >= EE) return;

    const long long* e64 = (const long long*)ei_raw;
    bool is64 = (((unsigned long long)e64[0] < (unsigned long long)NN) &&
                 ((unsigned long long)e64[1] < (unsigned long long)NN));
    int src, dst;
    if (is64) {
        src = (int)e64[e];
        dst = (int)e64[EE + e];
    } else {
        const int* e32 = (const int*)ei_raw;
        src = e32[e];
        dst = e32[EE + e];
    }
    float4 v = *(const float4*)(h + (size_t)src * DD + lane * 4);
    float* p = agg + (size_t)dst * DD + lane * 4;
    asm volatile("red.global.add.v4.f32 [%0], {%1, %2, %3, %4};"
                 :: "l"(p), "f"(v.x), "f"(v.y), "f"(v.z), "f"(v.w)
                 : "memory");
}

// ---------------- GRU gate fusion ----------------
static __device__ __forceinline__ float gate1(float ir, float iz, float in_,
                                              float hr, float hz, float hn, float hv) {
    float r = sigf(ir + hr);
    float z = sigf(iz + hz);
    float n = tanhf(in_ + r * hn);
    return (1.f - z) * n + z * hv;
}

__global__ void gru_gate(const float* __restrict__ gi, const float* __restrict__ gh,
                         float* __restrict__ h) {
    int t = blockIdx.x * blockDim.x + threadIdx.x;
    int n = t >> 5;
    int d4 = (t & 31) << 2;
    if (n >= NN) return;
    size_t bi = (size_t)n * 384 + d4;
    float4 ir = *(const float4*)(gi + bi);
    float4 iz = *(const float4*)(gi + bi + 128);
    float4 in_ = *(const float4*)(gi + bi + 256);
    float4 hr = *(const float4*)(gh + bi);
    float4 hz = *(const float4*)(gh + bi + 128);
    float4 hn = *(const float4*)(gh + bi + 256);
    float4* hp = (float4*)(h + (size_t)n * 128 + d4);
    float4 hv = *hp;
    float4 o;
    o.x = gate1(ir.x, iz.x, in_.x, hr.x, hz.x, hn.x, hv.x);
    o.y = gate1(ir.y, iz.y, in_.y, hr.y, hz.y, hn.y, hv.y);
    o.z = gate1(ir.z, iz.z, in_.z, hr.z, hz.z, hn.z, hv.z);
    o.w = gate1(ir.w, iz.w, in_.w, hr.w, hz.w, hn.w, hv.w);
    *hp = o;
}

// ---------------- launcher ----------------
extern "C" void kernel_launch(void* const* d_in, const int* in_sizes, int n_in,
                              void* d_out, int out_size) {
    const float* x     = (const float*)d_in[0];
    const void*  ei    = (const void*)d_in[1];
    const float* W1    = (const float*)d_in[2];
    const float* b1    = (const float*)d_in[3];
    const float* Wconv = (const float*)d_in[4];
    const float* Wih   = (const float*)d_in[5];
    const float* Whh   = (const float*)d_in[6];
    const float* bih   = (const float*)d_in[7];
    const float* bhh   = (const float*)d_in[8];
    const float* W2    = (const float*)d_in[9];
    const float* b2    = (const float*)d_in[10];
    float* out = (float*)d_out;

    float *h, *agg, *gi, *gh;
    cudaGetSymbolAddress((void**)&h, g_h);
    cudaGetSymbolAddress((void**)&agg, g_agg);
    cudaGetSymbolAddress((void**)&gi, g_gi);
    cudaGetSymbolAddress((void**)&gh, g_gh);

    cudaFuncSetAttribute(gemm_mma<0, 1, 1, 1>, cudaFuncAttributeMaxDynamicSharedMemorySize, SM_TOTAL);
    cudaFuncSetAttribute(gemm_mma<0, 0, 1, 3>, cudaFuncAttributeMaxDynamicSharedMemorySize, SM_TOTAL);
    cudaFuncSetAttribute(gemm_mma<1, 0, 1, 3>, cudaFuncAttributeMaxDynamicSharedMemorySize, SM_TOTAL);

    // side stream + fork/join events (created and destroyed every call; capture-safe)
    cudaStream_t s2;
    cudaStreamCreateWithFlags(&s2, cudaStreamNonBlocking);
    cudaEvent_t evH[3], evG[3];
    for (int i = 0; i < 3; i++) {
        cudaEventCreateWithFlags(&evH[i], cudaEventDisableTiming);
        cudaEventCreateWithFlags(&evG[i], cudaEventDisableTiming);
    }

    // prepasses: Wfused then split+swizzle all 16 tiles
    wfused_kernel<<<(3 * 384 * 128 + 255) / 256, 256>>>(Wih, Wconv);
    convert_w<<<(2048 * 128 + 255) / 256, 256>>>(W1, Whh, W2);

    // h = relu(x @ W1^T + b1)
    gemm_mma<0, 1, 1, 1><<<NT64, 256, SM_TOTAL>>>(x, 0, b1, h);

    for (int l = 0; l < 3; l++) {
        // fork: gh = h @ Whh^T + bhh on s2, overlapping zero+scatter+gi on main
        cudaEventRecord(evH[l], 0);
        cudaStreamWaitEvent(s2, evH[l], 0);
        gemm_mma<0, 0, 1, 3><<<NT64, 256, SM_TOTAL, s2>>>(h, 1, bhh, gh);
        cudaEventRecord(evG[l], s2);

        // main: agg = scatter(h); gi = agg @ Wfused[l]^T + bih
        zero_kernel<<<NN * DD / 4 / 256, 256>>>((float4*)agg);
        scatter_kernel<<<(EE * 32) / 256, 256>>>(h, ei, agg);
        gemm_mma<0, 0, 1, 3><<<NT64, 256, SM_TOTAL>>>(agg, 7 + 3 * l, bih, gi);

        // join, then h = GRU(gi, gh)
        cudaStreamWaitEvent(0, evG[l], 0);
        gru_gate<<<NN * 32 / 256, 256>>>(gi, gh, h);
    }

    // out = relu(h) @ W2^T + b2
    gemm_mma<1, 0, 1, 3><<<NT64, 256, SM_TOTAL>>>(h, 4, b2, out);

    for (int i = 0; i < 3; i++) {
        cudaEventDestroy(evH[i]);
        cudaEventDestroy(evG[i]);
    }
    cudaStreamDestroy(s2);
}

// round 10
// speedup vs baseline: 1.2167x; 1.0754x over previous
#include <cuda_runtime.h>
#include <cuda_bf16.h>
#include <cuda_fp16.h>
#include <cstdint>

#define NN 100000
#define DD 128
#define EE 600000
#define NT64 1563  // ceil(NN/64)

// ---------------- scratch (device globals: no runtime allocation) ----------------
__device__ float g_h[(size_t)NN * DD];
__device__ float g_agg[(size_t)NN * DD];       // scatter(h)
__device__ __half g_gi[(size_t)NN * 3 * DD];   // fp16 gate pre-activations
__device__ __half g_gh[(size_t)NN * 3 * DD];
__device__ float g_wf[3 * 384 * 128];          // Wfused[l] = Wih @ Wconv[l]
// pre-split, pre-swizzled weights: 16 tiles of 128x128 bf16 (32KB blobs)
// tile order: W1 (0), Whh (1-3), W2 (4-6), Wfused (7-15)
__device__ __nv_bfloat16 g_whi[16 * 16384];
__device__ __nv_bfloat16 g_wlo[16 * 16384];

// ---------------- helpers ----------------
static __device__ __forceinline__ uint32_t smem_u32(const void* p) {
    uint32_t a;
    asm("{ .reg .u64 t; cvta.to.shared.u64 t, %1; cvt.u32.u64 %0, t; }" : "=r"(a) : "l"(p));
    return a;
}
static __device__ __forceinline__ void ldsm4(uint32_t* r, uint32_t addr) {
    asm volatile("ldmatrix.sync.aligned.m8n8.x4.shared.b16 {%0,%1,%2,%3}, [%4];"
                 : "=r"(r[0]), "=r"(r[1]), "=r"(r[2]), "=r"(r[3]) : "r"(addr));
}
static __device__ __forceinline__ void mma16816(float* d, const uint32_t* a, const uint32_t* b) {
    asm volatile(
        "mma.sync.aligned.m16n8k16.row.col.f32.bf16.bf16.f32 "
        "{%0,%1,%2,%3}, {%4,%5,%6,%7}, {%8,%9}, {%0,%1,%2,%3};"
        : "+f"(d[0]), "+f"(d[1]), "+f"(d[2]), "+f"(d[3])
        : "r"(a[0]), "r"(a[1]), "r"(a[2]), "r"(a[3]), "r"(b[0]), "r"(b[1]));
}
static __device__ __forceinline__ void cpa16(uint32_t dst, const void* src) {
    asm volatile("cp.async.cg.shared.global [%0], [%1], 16;" :: "r"(dst), "l"(src) : "memory");
}
#define CP_COMMIT_WAIT() \
    asm volatile("cp.async.commit_group;\ncp.async.wait_group 0;" ::: "memory")

// swizzled byte offset within a tile (rows of 256B; 16B chunks XOR'd by row)
static __device__ __forceinline__ uint32_t swz(uint32_t r, uint32_t c2) {
    return r * 256 + (c2 ^ ((r & 7) << 4));
}

// Dekker split of 4 floats into bf16 hi/lo packed words
static __device__ __forceinline__ void split4(float4 v, uint2& hi, uint2& lo) {
    __nv_bfloat16 h0 = __float2bfloat16(v.x), h1 = __float2bfloat16(v.y);
    __nv_bfloat16 h2 = __float2bfloat16(v.z), h3 = __float2bfloat16(v.w);
    __nv_bfloat16 l0 = __float2bfloat16(v.x - __bfloat162float(h0));
    __nv_bfloat16 l1 = __float2bfloat16(v.y - __bfloat162float(h1));
    __nv_bfloat16 l2 = __float2bfloat16(v.z - __bfloat162float(h2));
    __nv_bfloat16 l3 = __float2bfloat16(v.w - __bfloat162float(h3));
    hi.x = (uint32_t)__bfloat16_as_ushort(h0) | ((uint32_t)__bfloat16_as_ushort(h1) << 16);
    hi.y = (uint32_t)__bfloat16_as_ushort(h2) | ((uint32_t)__bfloat16_as_ushort(h3) << 16);
    lo.x = (uint32_t)__bfloat16_as_ushort(l0) | ((uint32_t)__bfloat16_as_ushort(l1) << 16);
    lo.y = (uint32_t)__bfloat16_as_ushort(l2) | ((uint32_t)__bfloat16_as_ushort(l3) << 16);
}

static __device__ __forceinline__ float sigf(float x) { return 1.f / (1.f + __expf(-x)); }

// ---------------- prepass 1: Wfused[l] = Wih @ Wconv[l]  (fp32) ----------------
__global__ void wfused_kernel(const float* __restrict__ Wih, const float* __restrict__ Wconv) {
    int i = blockIdx.x * blockDim.x + threadIdx.x;  // 3*384*128
    if (i >= 3 * 384 * 128) return;
    int l = i / (384 * 128), r = (i >> 7) % 384, k = i & 127;
    const float* wc = Wconv + (size_t)l * 128 * 128;
    float s = 0.f;
#pragma unroll 8
    for (int j = 0; j < 128; j++) s = fmaf(__ldg(Wih + r * 128 + j), __ldg(wc + j * 128 + k), s);
    g_wf[i] = s;
}

// ---------------- prepass 2: split + swizzle all 16 weight tiles ----------------
// rows: [0,128) W1; [128,512) Whh; [512,896) W2; [896,2048) Wfused
__global__ void convert_w(const float* __restrict__ W1, const float* __restrict__ Whh,
                          const float* __restrict__ W2) {
    int i = blockIdx.x * blockDim.x + threadIdx.x;  // 2048*128 elements
    if (i >= 2048 * 128) return;
    int row = i >> 7, k = i & 127;
    float v;
    if (row < 128)       v = W1[(size_t)row * 128 + k];
    else if (row < 512)  v = Whh[(size_t)(row - 128) * 128 + k];
    else if (row < 896)  v = W2[(size_t)(row - 512) * 128 + k];
    else                 v = g_wf[(size_t)(row - 896) * 128 + k];
    __nv_bfloat16 h = __float2bfloat16(v);
    __nv_bfloat16 l = __float2bfloat16(v - __bfloat162float(h));
    int tile = row >> 7, tr = row & 127;
    uint32_t o = swz((uint32_t)tr, (uint32_t)(2 * k));
    *(__nv_bfloat16*)((char*)g_whi + (size_t)tile * 32768 + o) = h;
    *(__nv_bfloat16*)((char*)g_wlo + (size_t)tile * 32768 + o) = l;
}

// SMEM: A hi/lo (64x128 = 16KB each), B hi/lo (128x128 = 32KB each) = 96KB
#define SM_A_HI 0
#define SM_A_LO 16384
#define SM_B_HI 32768
#define SM_B_LO 65536
#define SM_TOTAL 98304

// ======== mma.sync GEMM: C[N, MT*128] = act( A[N,128] @ W^T + b ) ========
// Tile 64(M) x 128(N); 8 warps = 2 row x 4 col, warp tile 32x32; 3-term bf16 split.
// OUTH=1: C is __half* (fp16 stores). OUTH=0: C is float*.
template <int ACTIN, int ACTOUT, int BIAS, int MT, int OUTH>
__global__ __launch_bounds__(256, 2)
void gemm_mma(const float* __restrict__ A, int wtile0,
              const float* __restrict__ bias, void* __restrict__ Cv) {
    extern __shared__ char smem[];
    const uint32_t sb = smem_u32(smem);
    const int tid = threadIdx.x, lane = tid & 31, wid = tid >> 5;
    const int warp_m = (wid & 1) * 32;
    const int warp_n = (wid >> 1) * 32;
    const int n0 = blockIdx.x * 64;

    const int a_row = lane & 15;
    const int a_kh = (lane >> 4) & 1;
    const int b_row = (lane & 7) | (((lane >> 4) & 1) << 3);
    const int b_kh = (lane >> 3) & 1;

    // ---- fill + split A tile (64 rows x 128 k), once per CTA ----
    for (int i = tid; i < 2048; i += 256) {
        int r = i >> 5, k = (i & 31) << 2;
        int gr = n0 + r;
        if (gr >= NN) gr = NN - 1;  // clamp; padded rows discarded at store
        float4 v = *(const float4*)(A + (size_t)gr * 128 + k);
        if (ACTIN) {
            v.x = fmaxf(v.x, 0.f); v.y = fmaxf(v.y, 0.f);
            v.z = fmaxf(v.z, 0.f); v.w = fmaxf(v.w, 0.f);
        }
        uint2 hi, lo;
        split4(v, hi, lo);
        uint32_t o = swz((uint32_t)r, (uint32_t)(k * 2));
        *(uint2*)(smem + SM_A_HI + o) = hi;
        *(uint2*)(smem + SM_A_LO + o) = lo;
    }

    for (int mt = 0; mt < MT; mt++) {
        // ---- W fill: identity cp.async copy of pre-swizzled blobs ----
        const char* whb = (const char*)g_whi + (size_t)(wtile0 + mt) * 32768;
        const char* wlb = (const char*)g_wlo + (size_t)(wtile0 + mt) * 32768;
        for (int i = tid; i < 2048; i += 256) {
            cpa16(sb + SM_B_HI + i * 16, whb + i * 16);
            cpa16(sb + SM_B_LO + i * 16, wlb + i * 16);
        }
        CP_COMMIT_WAIT();
        __syncthreads();

        float acc[2][4][4];
#pragma unroll
        for (int t = 0; t < 2; t++)
#pragma unroll
            for (int u = 0; u < 4; u++)
#pragma unroll
                for (int q = 0; q < 4; q++) acc[t][u][q] = 0.f;

#pragma unroll 1
        for (int p = 0; p < 3; p++) {  // hi*hi, hi*lo, lo*hi
            const uint32_t Ab = sb + (p == 2 ? SM_A_LO : SM_A_HI);
            const uint32_t Bb = sb + (p == 1 ? SM_B_LO : SM_B_HI);
#pragma unroll
            for (int ks = 0; ks < 8; ks++) {
                const uint32_t c2a = ks * 32 + a_kh * 16;
                const uint32_t c2b = ks * 32 + b_kh * 16;
                uint32_t afr[2][4], bfr[4][2];
#pragma unroll
                for (int t = 0; t < 2; t++)
                    ldsm4(afr[t], Ab + swz(warp_m + t * 16 + a_row, c2a));
#pragma unroll
                for (int ub = 0; ub < 2; ub++) {
                    uint32_t tmp[4];
                    ldsm4(tmp, Bb + swz(warp_n + ub * 16 + b_row, c2b));
                    bfr[2 * ub][0] = tmp[0]; bfr[2 * ub][1] = tmp[1];
                    bfr[2 * ub + 1][0] = tmp[2]; bfr[2 * ub + 1][1] = tmp[3];
                }
#pragma unroll
                for (int t = 0; t < 2; t++)
#pragma unroll
                    for (int u = 0; u < 4; u++)
                        mma16816(acc[t][u], afr[t], bfr[u]);
            }
        }

        // ---- epilogue ----
        const int M = MT * 128;
        const int row0 = n0 + warp_m + (lane >> 2);
        const int colb = mt * 128 + warp_n + (lane & 3) * 2;
#pragma unroll
        for (int u = 0; u < 4; u++) {
            const int c = colb + u * 8;
            float b0 = 0.f, b1 = 0.f;
            if (BIAS) { b0 = __ldg(bias + c); b1 = __ldg(bias + c + 1); }
#pragma unroll
            for (int t = 0; t < 2; t++) {
                const int r = row0 + t * 16;
                float v0 = acc[t][u][0] + b0, v1 = acc[t][u][1] + b1;
                float v2 = acc[t][u][2] + b0, v3 = acc[t][u][3] + b1;
                if (ACTOUT) {
                    v0 = fmaxf(v0, 0.f); v1 = fmaxf(v1, 0.f);
                    v2 = fmaxf(v2, 0.f); v3 = fmaxf(v3, 0.f);
                }
                if (OUTH) {
                    __half2* C = (__half2*)Cv;
                    if (r < NN) C[((size_t)r * M + c) >> 1] = __floats2half2_rn(v0, v1);
                    if (r + 8 < NN) C[((size_t)(r + 8) * M + c) >> 1] = __floats2half2_rn(v2, v3);
                } else {
                    float* C = (float*)Cv;
                    if (r < NN) *(float2*)(C + (size_t)r * M + c) = make_float2(v0, v1);
                    if (r + 8 < NN) *(float2*)(C + (size_t)(r + 8) * M + c) = make_float2(v2, v3);
                }
            }
        }
        if (MT > 1) __syncthreads();  // B consumed before next mt overwrites
    }
}

// ---------------- zero agg ----------------
__global__ void zero_kernel(float4* __restrict__ p) {
    int i = blockIdx.x * blockDim.x + threadIdx.x;
    p[i] = make_float4(0.f, 0.f, 0.f, 0.f);
}

// ---------------- scatter-add: agg[dst] += h[src], warp per edge (REDG v4) ----------------
__global__ void scatter_kernel(const float* __restrict__ h,
                               const void* __restrict__ ei_raw,
                               float* __restrict__ agg) {
    int t = blockIdx.x * blockDim.x + threadIdx.x;
    int e = t >> 5;
    int lane = t & 31;
    if (e >= EE) return;

    const long long* e64 = (const long long*)ei_raw;
    bool is64 = (((unsigned long long)e64[0] < (unsigned long long)NN) &&
                 ((unsigned long long)e64[1] < (unsigned long long)NN));
    int src, dst;
    if (is64) {
        src = (int)e64[e];
        dst = (int)e64[EE + e];
    } else {
        const int* e32 = (const int*)ei_raw;
        src = e32[e];
        dst = e32[EE + e];
    }
    float4 v = *(const float4*)(h + (size_t)src * DD + lane * 4);
    float* p = agg + (size_t)dst * DD + lane * 4;
    asm volatile("red.global.add.v4.f32 [%0], {%1, %2, %3, %4};"
                 :: "l"(p), "f"(v.x), "f"(v.y), "f"(v.z), "f"(v.w)
                 : "memory");
}

// ---------------- GRU gate fusion (fp16 gi/gh inputs) ----------------
static __device__ __forceinline__ float gate1(float ir, float iz, float in_,
                                              float hr, float hz, float hn, float hv) {
    float r = sigf(ir + hr);
    float z = sigf(iz + hz);
    float n = tanhf(in_ + r * hn);
    return (1.f - z) * n + z * hv;
}

__global__ void gru_gate(const __half2* __restrict__ gi, const __half2* __restrict__ gh,
                         float* __restrict__ h) {
    int t = blockIdx.x * blockDim.x + threadIdx.x;  // NN*32 threads, 4 dims each
    int n = t >> 5;
    int d4 = (t & 31) << 2;
    if (n >= NN) return;
    size_t bi = ((size_t)n * 384 + d4) >> 1;  // half2 index
    float2 ir01 = __half22float2(gi[bi]),       ir23 = __half22float2(gi[bi + 1]);
    float2 iz01 = __half22float2(gi[bi + 64]),  iz23 = __half22float2(gi[bi + 65]);
    float2 in01 = __half22float2(gi[bi + 128]), in23 = __half22float2(gi[bi + 129]);
    float2 hr01 = __half22float2(gh[bi]),       hr23 = __half22float2(gh[bi + 1]);
    float2 hz01 = __half22float2(gh[bi + 64]),  hz23 = __half22float2(gh[bi + 65]);
    float2 hn01 = __half22float2(gh[bi + 128]), hn23 = __half22float2(gh[bi + 129]);
    float4* hp = (float4*)(h + (size_t)n * 128 + d4);
    float4 hv = *hp;
    float4 o;
    o.x = gate1(ir01.x, iz01.x, in01.x, hr01.x, hz01.x, hn01.x, hv.x);
    o.y = gate1(ir01.y, iz01.y, in01.y, hr01.y, hz01.y, hn01.y, hv.y);
    o.z = gate1(ir23.x, iz23.x, in23.x, hr23.x, hz23.x, hn23.x, hv.z);
    o.w = gate1(ir23.y, iz23.y, in23.y, hr23.y, hz23.y, hn23.y, hv.w);
    *hp = o;
}

// ---------------- launcher ----------------
extern "C" void kernel_launch(void* const* d_in, const int* in_sizes, int n_in,
                              void* d_out, int out_size) {
    const float* x     = (const float*)d_in[0];
    const void*  ei    = (const void*)d_in[1];
    const float* W1    = (const float*)d_in[2];
    const float* b1    = (const float*)d_in[3];
    const float* Wconv = (const float*)d_in[4];
    const float* Wih   = (const float*)d_in[5];
    const float* Whh   = (const float*)d_in[6];
    const float* bih   = (const float*)d_in[7];
    const float* bhh   = (const float*)d_in[8];
    const float* W2    = (const float*)d_in[9];
    const float* b2    = (const float*)d_in[10];
    float* out = (float*)d_out;

    float *h, *agg;
    __half *gi, *gh;
    cudaGetSymbolAddress((void**)&h, g_h);
    cudaGetSymbolAddress((void**)&agg, g_agg);
    cudaGetSymbolAddress((void**)&gi, g_gi);
    cudaGetSymbolAddress((void**)&gh, g_gh);

    cudaFuncSetAttribute(gemm_mma<0, 1, 1, 1, 0>, cudaFuncAttributeMaxDynamicSharedMemorySize, SM_TOTAL);
    cudaFuncSetAttribute(gemm_mma<0, 0, 1, 3, 1>, cudaFuncAttributeMaxDynamicSharedMemorySize, SM_TOTAL);
    cudaFuncSetAttribute(gemm_mma<1, 0, 1, 3, 0>, cudaFuncAttributeMaxDynamicSharedMemorySize, SM_TOTAL);

    // side stream + fork/join events (created and destroyed every call; capture-safe)
    cudaStream_t s2;
    cudaStreamCreateWithFlags(&s2, cudaStreamNonBlocking);
    cudaEvent_t evH[3], evG[3];
    for (int i = 0; i < 3; i++) {
        cudaEventCreateWithFlags(&evH[i], cudaEventDisableTiming);
        cudaEventCreateWithFlags(&evG[i], cudaEventDisableTiming);
    }

    // prepasses: Wfused then split+swizzle all 16 tiles
    wfused_kernel<<<(3 * 384 * 128 + 255) / 256, 256>>>(Wih, Wconv);
    convert_w<<<(2048 * 128 + 255) / 256, 256>>>(W1, Whh, W2);

    // h = relu(x @ W1^T + b1)
    gemm_mma<0, 1, 1, 1, 0><<<NT64, 256, SM_TOTAL>>>(x, 0, b1, h);

    for (int l = 0; l < 3; l++) {
        // fork: gh = h @ Whh^T + bhh on s2, overlapping zero+scatter+gi on main
        cudaEventRecord(evH[l], 0);
        cudaStreamWaitEvent(s2, evH[l], 0);
        gemm_mma<0, 0, 1, 3, 1><<<NT64, 256, SM_TOTAL, s2>>>(h, 1, bhh, gh);
        cudaEventRecord(evG[l], s2);

        // main: agg = scatter(h); gi = agg @ Wfused[l]^T + bih
        zero_kernel<<<NN * DD / 4 / 256, 256>>>((float4*)agg);
        scatter_kernel<<<(EE * 32) / 256, 256>>>(h, ei, agg);
        gemm_mma<0, 0, 1, 3, 1><<<NT64, 256, SM_TOTAL>>>(agg, 7 + 3 * l, bih, gi);

        // join, then h = GRU(gi, gh)
        cudaStreamWaitEvent(0, evG[l], 0);
        gru_gate<<<NN * 32 / 256, 256>>>((const __half2*)gi, (const __half2*)gh, h);
    }

    // out = relu(h) @ W2^T + b2
    gemm_mma<1, 0, 1, 3, 0><<<NT64, 256, SM_TOTAL>>>(h, 4, b2, out);

    for (int i = 0; i < 3; i++) {
        cudaEventDestroy(evH[i]);
        cudaEventDestroy(evG[i]);
    }
    cudaStreamDestroy(s2);
}

// round 11
// speedup vs baseline: 1.5002x; 1.2330x over previous
#include <cuda_runtime.h>
#include <cuda_fp16.h>
#include <cstdint>

#define NN 100000
#define DD 128
#define EE 600000
#define NT64 1563  // ceil(NN/64)

// ---------------- scratch (device globals: no runtime allocation) ----------------
__device__ float g_h[(size_t)NN * DD];
__device__ float g_agg[(size_t)NN * DD];       // scatter(h)
__device__ __half g_gi[(size_t)NN * 3 * DD];   // fp16 gate pre-activations
__device__ __half g_gh[(size_t)NN * 3 * DD];
__device__ float g_wf[3 * 384 * 128];          // Wfused[l] = Wih @ Wconv[l]
// pre-converted, pre-swizzled fp16 weights: 16 tiles of 128x128 (32KB blobs)
// tile order: W1 (0), Whh (1-3), W2 (4-6), Wfused (7-15)
__device__ __half g_wh[16 * 16384];

// ---------------- helpers ----------------
static __device__ __forceinline__ uint32_t smem_u32(const void* p) {
    uint32_t a;
    asm("{ .reg .u64 t; cvta.to.shared.u64 t, %1; cvt.u32.u64 %0, t; }" : "=r"(a) : "l"(p));
    return a;
}
static __device__ __forceinline__ void ldsm4(uint32_t* r, uint32_t addr) {
    asm volatile("ldmatrix.sync.aligned.m8n8.x4.shared.b16 {%0,%1,%2,%3}, [%4];"
                 : "=r"(r[0]), "=r"(r[1]), "=r"(r[2]), "=r"(r[3]) : "r"(addr));
}
// fp16 mma m16n8k16, fp32 accumulate in place
static __device__ __forceinline__ void mma16816(float* d, const uint32_t* a, const uint32_t* b) {
    asm volatile(
        "mma.sync.aligned.m16n8k16.row.col.f32.f16.f16.f32 "
        "{%0,%1,%2,%3}, {%4,%5,%6,%7}, {%8,%9}, {%0,%1,%2,%3};"
        : "+f"(d[0]), "+f"(d[1]), "+f"(d[2]), "+f"(d[3])
        : "r"(a[0]), "r"(a[1]), "r"(a[2]), "r"(a[3]), "r"(b[0]), "r"(b[1]));
}
static __device__ __forceinline__ void cpa16(uint32_t dst, const void* src) {
    asm volatile("cp.async.cg.shared.global [%0], [%1], 16;" :: "r"(dst), "l"(src) : "memory");
}
#define CP_COMMIT_WAIT() \
    asm volatile("cp.async.commit_group;\ncp.async.wait_group 0;" ::: "memory")

// swizzled byte offset within a tile (rows of 256B; 16B chunks XOR'd by row)
static __device__ __forceinline__ uint32_t swz(uint32_t r, uint32_t c2) {
    return r * 256 + (c2 ^ ((r & 7) << 4));
}

// Dekker split of 4 floats into fp16 hi/lo packed words (~22-bit effective mantissa)
static __device__ __forceinline__ void split4h(float4 v, uint2& hi, uint2& lo) {
    __half h0 = __float2half(v.x), h1 = __float2half(v.y);
    __half h2 = __float2half(v.z), h3 = __float2half(v.w);
    __half l0 = __float2half(v.x - __half2float(h0));
    __half l1 = __float2half(v.y - __half2float(h1));
    __half l2 = __float2half(v.z - __half2float(h2));
    __half l3 = __float2half(v.w - __half2float(h3));
    hi.x = (uint32_t)__half_as_ushort(h0) | ((uint32_t)__half_as_ushort(h1) << 16);
    hi.y = (uint32_t)__half_as_ushort(h2) | ((uint32_t)__half_as_ushort(h3) << 16);
    lo.x = (uint32_t)__half_as_ushort(l0) | ((uint32_t)__half_as_ushort(l1) << 16);
    lo.y = (uint32_t)__half_as_ushort(l2) | ((uint32_t)__half_as_ushort(l3) << 16);
}

static __device__ __forceinline__ float sigf(float x) { return 1.f / (1.f + __expf(-x)); }

// ---------------- prepass 1: Wfused[l] = Wih @ Wconv[l]  (fp32) ----------------
__global__ void wfused_kernel(const float* __restrict__ Wih, const float* __restrict__ Wconv) {
    int i = blockIdx.x * blockDim.x + threadIdx.x;  // 3*384*128
    if (i >= 3 * 384 * 128) return;
    int l = i / (384 * 128), r = (i >> 7) % 384, k = i & 127;
    const float* wc = Wconv + (size_t)l * 128 * 128;
    float s = 0.f;
#pragma unroll 8
    for (int j = 0; j < 128; j++) s = fmaf(__ldg(Wih + r * 128 + j), __ldg(wc + j * 128 + k), s);
    g_wf[i] = s;
}

// ---------------- prepass 2: convert + swizzle all 16 weight tiles to fp16 ----------------
// rows: [0,128) W1; [128,512) Whh; [512,896) W2; [896,2048) Wfused
__global__ void convert_w(const float* __restrict__ W1, const float* __restrict__ Whh,
                          const float* __restrict__ W2) {
    int i = blockIdx.x * blockDim.x + threadIdx.x;  // 2048*128 elements
    if (i >= 2048 * 128) return;
    int row = i >> 7, k = i & 127;
    float v;
    if (row < 128)       v = W1[(size_t)row * 128 + k];
    else if (row < 512)  v = Whh[(size_t)(row - 128) * 128 + k];
    else if (row < 896)  v = W2[(size_t)(row - 512) * 128 + k];
    else                 v = g_wf[(size_t)(row - 896) * 128 + k];
    int tile = row >> 7, tr = row & 127;
    uint32_t o = swz((uint32_t)tr, (uint32_t)(2 * k));
    *(__half*)((char*)g_wh + (size_t)tile * 32768 + o) = __float2half(v);
}

// SMEM: A hi/lo (64x128 = 16KB each), B (128x128 = 32KB) = 64KB -> occ 3
#define SM_A_HI 0
#define SM_A_LO 16384
#define SM_B 32768
#define SM_TOTAL 65536

// ======== mma.sync GEMM: C[N, MT*128] = act( A[N,128] @ W^T + b ) ========
// Tile 64(M) x 128(N); 8 warps = 2 row x 4 col, warp tile 32x32.
// 2-pass fp16 split: A_hi@B + A_lo@B (B single fp16).
// OUTH=1: C is __half* (fp16 stores). OUTH=0: C is float*.
template <int ACTIN, int ACTOUT, int BIAS, int MT, int OUTH>
__global__ __launch_bounds__(256, 3)
void gemm_mma(const float* __restrict__ A, int wtile0,
              const float* __restrict__ bias, void* __restrict__ Cv) {
    extern __shared__ char smem[];
    const uint32_t sb = smem_u32(smem);
    const int tid = threadIdx.x, lane = tid & 31, wid = tid >> 5;
    const int warp_m = (wid & 1) * 32;
    const int warp_n = (wid >> 1) * 32;
    const int n0 = blockIdx.x * 64;

    const int a_row = lane & 15;
    const int a_kh = (lane >> 4) & 1;
    const int b_row = (lane & 7) | (((lane >> 4) & 1) << 3);
    const int b_kh = (lane >> 3) & 1;

    // ---- fill + split A tile (64 rows x 128 k), once per CTA ----
    for (int i = tid; i < 2048; i += 256) {
        int r = i >> 5, k = (i & 31) << 2;
        int gr = n0 + r;
        if (gr >= NN) gr = NN - 1;  // clamp; padded rows discarded at store
        float4 v = *(const float4*)(A + (size_t)gr * 128 + k);
        if (ACTIN) {
            v.x = fmaxf(v.x, 0.f); v.y = fmaxf(v.y, 0.f);
            v.z = fmaxf(v.z, 0.f); v.w = fmaxf(v.w, 0.f);
        }
        uint2 hi, lo;
        split4h(v, hi, lo);
        uint32_t o = swz((uint32_t)r, (uint32_t)(k * 2));
        *(uint2*)(smem + SM_A_HI + o) = hi;
        *(uint2*)(smem + SM_A_LO + o) = lo;
    }

    for (int mt = 0; mt < MT; mt++) {
        // ---- W fill: identity cp.async copy of the pre-swizzled fp16 blob ----
        const char* wb = (const char*)g_wh + (size_t)(wtile0 + mt) * 32768;
        for (int i = tid; i < 2048; i += 256) {
            cpa16(sb + SM_B + i * 16, wb + i * 16);
        }
        CP_COMMIT_WAIT();
        __syncthreads();

        float acc[2][4][4];
#pragma unroll
        for (int t = 0; t < 2; t++)
#pragma unroll
            for (int u = 0; u < 4; u++)
#pragma unroll
                for (int q = 0; q < 4; q++) acc[t][u][q] = 0.f;

#pragma unroll 1
        for (int p = 0; p < 2; p++) {  // A_hi @ B, A_lo @ B
            const uint32_t Ab = sb + (p ? SM_A_LO : SM_A_HI);
#pragma unroll
            for (int ks = 0; ks < 8; ks++) {
                const uint32_t c2a = ks * 32 + a_kh * 16;
                const uint32_t c2b = ks * 32 + b_kh * 16;
                uint32_t afr[2][4], bfr[4][2];
#pragma unroll
                for (int t = 0; t < 2; t++)
                    ldsm4(afr[t], Ab + swz(warp_m + t * 16 + a_row, c2a));
#pragma unroll
                for (int ub = 0; ub < 2; ub++) {
                    uint32_t tmp[4];
                    ldsm4(tmp, sb + SM_B + swz(warp_n + ub * 16 + b_row, c2b));
                    bfr[2 * ub][0] = tmp[0]; bfr[2 * ub][1] = tmp[1];
                    bfr[2 * ub + 1][0] = tmp[2]; bfr[2 * ub + 1][1] = tmp[3];
                }
#pragma unroll
                for (int t = 0; t < 2; t++)
#pragma unroll
                    for (int u = 0; u < 4; u++)
                        mma16816(acc[t][u], afr[t], bfr[u]);
            }
        }

        // ---- epilogue ----
        const int M = MT * 128;
        const int row0 = n0 + warp_m + (lane >> 2);
        const int colb = mt * 128 + warp_n + (lane & 3) * 2;
#pragma unroll
        for (int u = 0; u < 4; u++) {
            const int c = colb + u * 8;
            float b0 = 0.f, b1 = 0.f;
            if (BIAS) { b0 = __ldg(bias + c); b1 = __ldg(bias + c + 1); }
#pragma unroll
            for (int t = 0; t < 2; t++) {
                const int r = row0 + t * 16;
                float v0 = acc[t][u][0] + b0, v1 = acc[t][u][1] + b1;
                float v2 = acc[t][u][2] + b0, v3 = acc[t][u][3] + b1;
                if (ACTOUT) {
                    v0 = fmaxf(v0, 0.f); v1 = fmaxf(v1, 0.f);
                    v2 = fmaxf(v2, 0.f); v3 = fmaxf(v3, 0.f);
                }
                if (OUTH) {
                    __half2* C = (__half2*)Cv;
                    if (r < NN) C[((size_t)r * M + c) >> 1] = __floats2half2_rn(v0, v1);
                    if (r + 8 < NN) C[((size_t)(r + 8) * M + c) >> 1] = __floats2half2_rn(v2, v3);
                } else {
                    float* C = (float*)Cv;
                    if (r < NN) *(float2*)(C + (size_t)r * M + c) = make_float2(v0, v1);
                    if (r + 8 < NN) *(float2*)(C + (size_t)(r + 8) * M + c) = make_float2(v2, v3);
                }
            }
        }
        if (MT > 1) __syncthreads();  // B consumed before next mt overwrites
    }
}

// ---------------- zero agg ----------------
__global__ void zero_kernel(float4* __restrict__ p) {
    int i = blockIdx.x * blockDim.x + threadIdx.x;
    p[i] = make_float4(0.f, 0.f, 0.f, 0.f);
}

// ---------------- scatter-add: agg[dst] += h[src], warp per edge (REDG v4) ----------------
__global__ void scatter_kernel(const float* __restrict__ h,
                               const void* __restrict__ ei_raw,
                               float* __restrict__ agg) {
    int t = blockIdx.x * blockDim.x + threadIdx.x;
    int e = t >> 5;
    int lane = t & 31;
    if (e >= EE) return;

    const long long* e64 = (const long long*)ei_raw;
    bool is64 = (((unsigned long long)e64[0] < (unsigned long long)NN) &&
                 ((unsigned long long)e64[1] < (unsigned long long)NN));
    int src, dst;
    if (is64) {
        src = (int)e64[e];
        dst = (int)e64[EE + e];
    } else {
        const int* e32 = (const int*)ei_raw;
        src = e32[e];
        dst = e32[EE + e];
    }
    float4 v = *(const float4*)(h + (size_t)src * DD + lane * 4);
    float* p = agg + (size_t)dst * DD + lane * 4;
    asm volatile("red.global.add.v4.f32 [%0], {%1, %2, %3, %4};"
                 :: "l"(p), "f"(v.x), "f"(v.y), "f"(v.z), "f"(v.w)
                 : "memory");
}

// ---------------- GRU gate fusion (fp16 gi/gh inputs) ----------------
static __device__ __forceinline__ float gate1(float ir, float iz, float in_,
                                              float hr, float hz, float hn, float hv) {
    float r = sigf(ir + hr);
    float z = sigf(iz + hz);
    float n = tanhf(in_ + r * hn);
    return (1.f - z) * n + z * hv;
}

__global__ void gru_gate(const __half2* __restrict__ gi, const __half2* __restrict__ gh,
                         float* __restrict__ h) {
    int t = blockIdx.x * blockDim.x + threadIdx.x;  // NN*32 threads, 4 dims each
    int n = t >> 5;
    int d4 = (t & 31) << 2;
    if (n >= NN) return;
    size_t bi = ((size_t)n * 384 + d4) >> 1;  // half2 index
    float2 ir01 = __half22float2(gi[bi]),       ir23 = __half22float2(gi[bi + 1]);
    float2 iz01 = __half22float2(gi[bi + 64]),  iz23 = __half22float2(gi[bi + 65]);
    float2 in01 = __half22float2(gi[bi + 128]), in23 = __half22float2(gi[bi + 129]);
    float2 hr01 = __half22float2(gh[bi]),       hr23 = __half22float2(gh[bi + 1]);
    float2 hz01 = __half22float2(gh[bi + 64]),  hz23 = __half22float2(gh[bi + 65]);
    float2 hn01 = __half22float2(gh[bi + 128]), hn23 = __half22float2(gh[bi + 129]);
    float4* hp = (float4*)(h + (size_t)n * 128 + d4);
    float4 hv = *hp;
    float4 o;
    o.x = gate1(ir01.x, iz01.x, in01.x, hr01.x, hz01.x, hn01.x, hv.x);
    o.y = gate1(ir01.y, iz01.y, in01.y, hr01.y, hz01.y, hn01.y, hv.y);
    o.z = gate1(ir23.x, iz23.x, in23.x, hr23.x, hz23.x, hn23.x, hv.z);
    o.w = gate1(ir23.y, iz23.y, in23.y, hr23.y, hz23.y, hn23.y, hv.w);
    *hp = o;
}

// ---------------- launcher ----------------
extern "C" void kernel_launch(void* const* d_in, const int* in_sizes, int n_in,
                              void* d_out, int out_size) {
    const float* x     = (const float*)d_in[0];
    const void*  ei    = (const void*)d_in[1];
    const float* W1    = (const float*)d_in[2];
    const float* b1    = (const float*)d_in[3];
    const float* Wconv = (const float*)d_in[4];
    const float* Wih   = (const float*)d_in[5];
    const float* Whh   = (const float*)d_in[6];
    const float* bih   = (const float*)d_in[7];
    const float* bhh   = (const float*)d_in[8];
    const float* W2    = (const float*)d_in[9];
    const float* b2    = (const float*)d_in[10];
    float* out = (float*)d_out;

    float *h, *agg;
    __half *gi, *gh;
    cudaGetSymbolAddress((void**)&h, g_h);
    cudaGetSymbolAddress((void**)&agg, g_agg);
    cudaGetSymbolAddress((void**)&gi, g_gi);
    cudaGetSymbolAddress((void**)&gh, g_gh);

    cudaFuncSetAttribute(gemm_mma<0, 1, 1, 1, 0>, cudaFuncAttributeMaxDynamicSharedMemorySize, SM_TOTAL);
    cudaFuncSetAttribute(gemm_mma<0, 0, 1, 3, 1>, cudaFuncAttributeMaxDynamicSharedMemorySize, SM_TOTAL);
    cudaFuncSetAttribute(gemm_mma<1, 0, 1, 3, 0>, cudaFuncAttributeMaxDynamicSharedMemorySize, SM_TOTAL);

    // side stream + fork/join events (created and destroyed every call; capture-safe)
    cudaStream_t s2;
    cudaStreamCreateWithFlags(&s2, cudaStreamNonBlocking);
    cudaEvent_t evH[3], evG[3];
    for (int i = 0; i < 3; i++) {
        cudaEventCreateWithFlags(&evH[i], cudaEventDisableTiming);
        cudaEventCreateWithFlags(&evG[i], cudaEventDisableTiming);
    }

    // prepasses: Wfused then convert+swizzle all 16 tiles to fp16
    wfused_kernel<<<(3 * 384 * 128 + 255) / 256, 256>>>(Wih, Wconv);
    convert_w<<<(2048 * 128 + 255) / 256, 256>>>(W1, Whh, W2);

    // h = relu(x @ W1^T + b1)
    gemm_mma<0, 1, 1, 1, 0><<<NT64, 256, SM_TOTAL>>>(x, 0, b1, h);

    for (int l = 0; l < 3; l++) {
        // fork: gh = h @ Whh^T + bhh on s2, overlapping zero+scatter on main
        cudaEventRecord(evH[l], 0);
        cudaStreamWaitEvent(s2, evH[l], 0);
        gemm_mma<0, 0, 1, 3, 1><<<NT64, 256, SM_TOTAL, s2>>>(h, 1, bhh, gh);
        cudaEventRecord(evG[l], s2);

        // main: agg = scatter(h); gi = agg @ Wfused[l]^T + bih
        zero_kernel<<<NN * DD / 4 / 256, 256>>>((float4*)agg);
        scatter_kernel<<<(EE * 32) / 256, 256>>>(h, ei, agg);
        gemm_mma<0, 0, 1, 3, 1><<<NT64, 256, SM_TOTAL>>>(agg, 7 + 3 * l, bih, gi);

        // join, then h = GRU(gi, gh)
        cudaStreamWaitEvent(0, evG[l], 0);
        gru_gate<<<NN * 32 / 256, 256>>>((const __half2*)gi, (const __half2*)gh, h);
    }

    // out = relu(h) @ W2^T + b2
    gemm_mma<1, 0, 1, 3, 0><<<NT64, 256, SM_TOTAL>>>(h, 4, b2, out);

    for (int i = 0; i < 3; i++) {
        cudaEventDestroy(evH[i]);
        cudaEventDestroy(evG[i]);
    }
    cudaStreamDestroy(s2);
}